// round 1
// baseline (speedup 1.0000x reference)
#include <cuda_runtime.h>

#define STEPS 20
#define BATCH 512
#define DIM   2048
#define M_TOT (STEPS * BATCH)   // 10240
#define K_DIM DIM               // 2048
#define N_DIM DIM               // 2048

// Scratch for J = X @ W^T, [M_TOT, N_DIM] fp32 (~84 MB). Device global: no allocs.
__device__ float g_J[(size_t)M_TOT * N_DIM];

// ---------------------------------------------------------------------------
// GEMM (NT): J[m][n] = sum_k X[m][k] * W[n][k]
// X row-major [M_TOT, K], W row-major [N_DIM, K]  (both K-contiguous -> NT)
// Tile: BM=128, BN=128, BK=16, 256 threads, 8x8 per-thread micro-tile.
// ---------------------------------------------------------------------------
__global__ __launch_bounds__(256) void gemm_nt_kernel(const float* __restrict__ X,
                                                      const float* __restrict__ W) {
    __shared__ float As[16][128];   // As[k][m]
    __shared__ float Bs[16][128];   // Bs[k][n]

    const int bn = blockIdx.x;      // n tile
    const int bm = blockIdx.y;      // m tile
    const int tid = threadIdx.x;    // 0..255

    // Global load mapping: tile is 128 rows x 16 cols = 512 float4.
    // Thread t loads float4 #t and #(t+256): row = f>>2, col4 = (f&3)*4.
    const int lrow  = tid >> 2;          // 0..63  (second load: +64)
    const int lk    = (tid & 3) * 4;     // 0,4,8,12

    const float* Xp = X + (size_t)(bm * 128) * K_DIM + lk;
    const float* Wp = W + (size_t)(bn * 128) * K_DIM + lk;

    // Compute mapping: 16x16 thread grid, each owns 8x8 outputs.
    const int tx = tid & 15;   // n dir
    const int ty = tid >> 4;   // m dir

    float acc[8][8];
#pragma unroll
    for (int i = 0; i < 8; i++)
#pragma unroll
        for (int j = 0; j < 8; j++) acc[i][j] = 0.0f;

    for (int kt = 0; kt < K_DIM; kt += 16) {
        // Load X tile (transpose into As[k][m])
        {
            float4 a0 = *reinterpret_cast<const float4*>(Xp + (size_t)lrow * K_DIM + kt);
            float4 a1 = *reinterpret_cast<const float4*>(Xp + (size_t)(lrow + 64) * K_DIM + kt);
            As[lk + 0][lrow] = a0.x; As[lk + 1][lrow] = a0.y;
            As[lk + 2][lrow] = a0.z; As[lk + 3][lrow] = a0.w;
            As[lk + 0][lrow + 64] = a1.x; As[lk + 1][lrow + 64] = a1.y;
            As[lk + 2][lrow + 64] = a1.z; As[lk + 3][lrow + 64] = a1.w;

            float4 b0 = *reinterpret_cast<const float4*>(Wp + (size_t)lrow * K_DIM + kt);
            float4 b1 = *reinterpret_cast<const float4*>(Wp + (size_t)(lrow + 64) * K_DIM + kt);
            Bs[lk + 0][lrow] = b0.x; Bs[lk + 1][lrow] = b0.y;
            Bs[lk + 2][lrow] = b0.z; Bs[lk + 3][lrow] = b0.w;
            Bs[lk + 0][lrow + 64] = b1.x; Bs[lk + 1][lrow + 64] = b1.y;
            Bs[lk + 2][lrow + 64] = b1.z; Bs[lk + 3][lrow + 64] = b1.w;
        }
        __syncthreads();

#pragma unroll
        for (int k = 0; k < 16; k++) {
            float ra[8], rb[8];
            float4 a0 = *reinterpret_cast<const float4*>(&As[k][ty * 8]);
            float4 a1 = *reinterpret_cast<const float4*>(&As[k][ty * 8 + 4]);
            ra[0] = a0.x; ra[1] = a0.y; ra[2] = a0.z; ra[3] = a0.w;
            ra[4] = a1.x; ra[5] = a1.y; ra[6] = a1.z; ra[7] = a1.w;
            float4 b0 = *reinterpret_cast<const float4*>(&Bs[k][tx * 8]);
            float4 b1 = *reinterpret_cast<const float4*>(&Bs[k][tx * 8 + 4]);
            rb[0] = b0.x; rb[1] = b0.y; rb[2] = b0.z; rb[3] = b0.w;
            rb[4] = b1.x; rb[5] = b1.y; rb[6] = b1.z; rb[7] = b1.w;
#pragma unroll
            for (int i = 0; i < 8; i++)
#pragma unroll
                for (int j = 0; j < 8; j++)
                    acc[i][j] = fmaf(ra[i], rb[j], acc[i][j]);
        }
        __syncthreads();
    }

    // Store: J[(bm*128 + ty*8 + i)][(bn*128 + tx*8 + j)]
    float* Jp = g_J + (size_t)(bm * 128 + ty * 8) * N_DIM + (bn * 128 + tx * 8);
#pragma unroll
    for (int i = 0; i < 8; i++) {
        float4 c0 = make_float4(acc[i][0], acc[i][1], acc[i][2], acc[i][3]);
        float4 c1 = make_float4(acc[i][4], acc[i][5], acc[i][6], acc[i][7]);
        *reinterpret_cast<float4*>(Jp + (size_t)i * N_DIM)     = c0;
        *reinterpret_cast<float4*>(Jp + (size_t)i * N_DIM + 4) = c1;
    }
}

// ---------------------------------------------------------------------------
// LIF scan: per (b, o) element, sequential over t.
//   V_new = a_m*V + (dt/tau_m)*I ; s = (V_new >= 1) ; V = V_new*(1-s)
//   I = a_s*I + J_t ; out[t] = s
// ---------------------------------------------------------------------------
__global__ __launch_bounds__(256) void lif_scan_kernel(float* __restrict__ out) {
    const int idx = blockIdx.x * blockDim.x + threadIdx.x;
    const size_t stride = (size_t)BATCH * DIM;
    float V = 0.0f, I = 0.0f;
#pragma unroll
    for (int t = 0; t < STEPS; t++) {
        float Vn = 0.95f * V + 0.05f * I;
        float s = (Vn >= 1.0f) ? 1.0f : 0.0f;
        V = Vn * (1.0f - s);
        I = 0.8f * I + g_J[(size_t)t * stride + idx];
        out[(size_t)t * stride + idx] = s;
    }
}

extern "C" void kernel_launch(void* const* d_in, const int* in_sizes, int n_in,
                              void* d_out, int out_size) {
    const float* x = (const float*)d_in[0];   // [20, 512, 2048] spikes
    const float* W = (const float*)d_in[1];   // [2048, 2048]
    float* out = (float*)d_out;               // [20, 512, 2048]

    dim3 ggrid(N_DIM / 128, M_TOT / 128);     // (16, 80)
    gemm_nt_kernel<<<ggrid, 256>>>(x, W);

    const int total = BATCH * DIM;            // 1,048,576
    lif_scan_kernel<<<total / 256, 256>>>(out);
}

// round 3
// speedup vs baseline: 3.8243x; 3.8243x over previous
#include <cuda_runtime.h>
#include <cuda_bf16.h>
#include <cstdint>

#define STEPS 20
#define BATCH 512
#define DIM   2048
#define M_TOT (STEPS * BATCH)   // 10240
#define K_DIM DIM               // 2048
#define N_DIM DIM               // 2048

#define BM 128
#define BN 128
#define BK 32
#define NKITER (K_DIM / BK)      // 64
#define NSTAGE 3
#define SROW 40                                  // padded smem row stride (elements)
#define TILE_B (128 * SROW * 2)                  // 10240 B per 128x32 bf16 tile
#define STAGE_B (3 * TILE_B)                     // A + Bh + Bl = 30720 B
#define SMEM_TOTAL (NSTAGE * STAGE_B)            // 92160 B

// ---------------- device globals (no allocs allowed) ----------------
__device__ __align__(256) __nv_bfloat16 g_Xb[(size_t)M_TOT * K_DIM];  // 42 MB
__device__ __align__(256) __nv_bfloat16 g_Wh[(size_t)N_DIM * K_DIM];  // 8 MB
__device__ __align__(256) __nv_bfloat16 g_Wl[(size_t)N_DIM * K_DIM];  // 8 MB
__device__ __align__(256) float         g_J [(size_t)M_TOT * N_DIM];  // 84 MB

// ---------------- PTX helpers ----------------
__device__ __forceinline__ uint32_t smem_u32(const void* p) {
    uint32_t a;
    asm("{ .reg .u64 t; cvta.to.shared.u64 t, %1; cvt.u32.u64 %0, t; }" : "=r"(a) : "l"(p));
    return a;
}
__device__ __forceinline__ void cp16(uint32_t s, const void* g) {
    asm volatile("cp.async.cg.shared.global [%0], [%1], 16;" :: "r"(s), "l"(g));
}
#define CP_COMMIT() asm volatile("cp.async.commit_group;" ::: "memory")

#define LDMX4(r0, r1, r2, r3, a) \
    asm volatile("ldmatrix.sync.aligned.m8n8.x4.shared.b16 {%0,%1,%2,%3}, [%4];" \
                 : "=r"(r0), "=r"(r1), "=r"(r2), "=r"(r3) : "r"(a))

#define MMA16816(c, a0, a1, a2, a3, b0, b1) \
    asm volatile("mma.sync.aligned.m16n8k16.row.col.f32.bf16.bf16.f32 " \
                 "{%0,%1,%2,%3}, {%4,%5,%6,%7}, {%8,%9}, {%0,%1,%2,%3};" \
                 : "+f"((c)[0]), "+f"((c)[1]), "+f"((c)[2]), "+f"((c)[3]) \
                 : "r"(a0), "r"(a1), "r"(a2), "r"(a3), "r"(b0), "r"(b1))

// ---------------- conversion kernels ----------------
__global__ __launch_bounds__(256) void conv_x_kernel(const float* __restrict__ x) {
    size_t i = ((size_t)blockIdx.x * 256 + threadIdx.x) * 4;
    float4 v = *reinterpret_cast<const float4*>(x + i);
    *reinterpret_cast<__nv_bfloat162*>(g_Xb + i)     = __floats2bfloat162_rn(v.x, v.y);
    *reinterpret_cast<__nv_bfloat162*>(g_Xb + i + 2) = __floats2bfloat162_rn(v.z, v.w);
}

__global__ __launch_bounds__(256) void conv_w_kernel(const float* __restrict__ w) {
    size_t i = ((size_t)blockIdx.x * 256 + threadIdx.x) * 4;
    float4 v = *reinterpret_cast<const float4*>(w + i);
    __nv_bfloat16 h0 = __float2bfloat16(v.x), h1 = __float2bfloat16(v.y);
    __nv_bfloat16 h2 = __float2bfloat16(v.z), h3 = __float2bfloat16(v.w);
    __nv_bfloat162 hi01; hi01.x = h0; hi01.y = h1;
    __nv_bfloat162 hi23; hi23.x = h2; hi23.y = h3;
    *reinterpret_cast<__nv_bfloat162*>(g_Wh + i)     = hi01;
    *reinterpret_cast<__nv_bfloat162*>(g_Wh + i + 2) = hi23;
    *reinterpret_cast<__nv_bfloat162*>(g_Wl + i) =
        __floats2bfloat162_rn(v.x - __bfloat162float(h0), v.y - __bfloat162float(h1));
    *reinterpret_cast<__nv_bfloat162*>(g_Wl + i + 2) =
        __floats2bfloat162_rn(v.z - __bfloat162float(h2), v.w - __bfloat162float(h3));
}

// ---------------- HMMA GEMM: J = Xb @ (Wh + Wl)^T ----------------
// Block 128x128x32, 8 warps (2m x 4n), warp tile 64x32, frags m16n8k16.
__global__ __launch_bounds__(256, 2) void gemm_hmma_kernel() {
    extern __shared__ char smem[];
    const uint32_t sbase = smem_u32(smem);

    const int tid = threadIdx.x;
    const int wid = tid >> 5;
    const int lid = tid & 31;
    const int wm = wid & 1;          // 0..1  (m slices of 64)
    const int wn = wid >> 1;         // 0..3  (n slices of 32)
    const int bn = blockIdx.x;       // 0..15
    const int bm = blockIdx.y;       // 0..79

    const __nv_bfloat16* Ag = g_Xb + (size_t)(bm * BM) * K_DIM;
    const __nv_bfloat16* Hg = g_Wh + (size_t)(bn * BN) * K_DIM;
    const __nv_bfloat16* Lg = g_Wl + (size_t)(bn * BN) * K_DIM;

    // per-stage smem offsets
    auto sA = [&](int s) { return sbase + s * STAGE_B; };
    auto sH = [&](int s) { return sbase + s * STAGE_B + TILE_B; };
    auto sL = [&](int s) { return sbase + s * STAGE_B + 2 * TILE_B; };

    // global->smem loads: 128 rows x 4 chunks(16B) per tile; 256 threads -> 2 chunks each
    const int c0r = tid >> 2;            // chunk row for c = tid
    const int c0c = (tid & 3) * 16;      // chunk byte offset in row
    const int c1r = (tid + 256) >> 2;
    const int c1c = ((tid + 256) & 3) * 16;

    auto load_stage = [&](int s, int kt) {
        const int kof = kt * BK;
        uint32_t a = sA(s), h = sH(s), l = sL(s);
        cp16(a + c0r * (SROW * 2) + c0c, Ag + (size_t)c0r * K_DIM + kof + c0c / 2);
        cp16(a + c1r * (SROW * 2) + c1c, Ag + (size_t)c1r * K_DIM + kof + c1c / 2);
        cp16(h + c0r * (SROW * 2) + c0c, Hg + (size_t)c0r * K_DIM + kof + c0c / 2);
        cp16(h + c1r * (SROW * 2) + c1c, Hg + (size_t)c1r * K_DIM + kof + c1c / 2);
        cp16(l + c0r * (SROW * 2) + c0c, Lg + (size_t)c0r * K_DIM + kof + c0c / 2);
        cp16(l + c1r * (SROW * 2) + c1c, Lg + (size_t)c1r * K_DIM + kof + c1c / 2);
        CP_COMMIT();
    };

    float acc[4][4][4];
#pragma unroll
    for (int i = 0; i < 4; i++)
#pragma unroll
        for (int j = 0; j < 4; j++)
#pragma unroll
            for (int r = 0; r < 4; r++) acc[i][j][r] = 0.0f;

    // ldmatrix per-thread address components (byte offsets within a tile)
    const int a_row = wm * 64 + (lid & 15);          // + mi*16
    const int a_kof = (lid >> 4) * 8;                // + ks*16
    const int b_row = wn * 32 + (lid & 7) + ((lid >> 4) << 3);   // + nj2*16
    const int b_kof = ((lid >> 3) & 1) * 8;                       // + ks*16

    // prologue
    load_stage(0, 0);
    load_stage(1, 1);

    for (int kt = 0; kt < NKITER; kt++) {
        if (kt < NKITER - 2) asm volatile("cp.async.wait_group 1;" ::: "memory");
        else                 asm volatile("cp.async.wait_group 0;" ::: "memory");
        __syncthreads();

        if (kt + 2 < NKITER) load_stage((kt + 2) % NSTAGE, kt + 2);

        const int s = kt % NSTAGE;
        const uint32_t aT = sA(s), hT = sH(s), lT = sL(s);

#pragma unroll
        for (int ks = 0; ks < 2; ks++) {
            uint32_t af[4][4];
#pragma unroll
            for (int mi = 0; mi < 4; mi++) {
                uint32_t addr = aT + (a_row + mi * 16) * (SROW * 2) + (a_kof + ks * 16) * 2;
                LDMX4(af[mi][0], af[mi][1], af[mi][2], af[mi][3], addr);
            }
#pragma unroll
            for (int nj2 = 0; nj2 < 2; nj2++) {
                uint32_t b0, b1, b2, b3;
                uint32_t addr = hT + (b_row + nj2 * 16) * (SROW * 2) + (b_kof + ks * 16) * 2;
                LDMX4(b0, b1, b2, b3, addr);
#pragma unroll
                for (int mi = 0; mi < 4; mi++) {
                    MMA16816(acc[mi][nj2 * 2],     af[mi][0], af[mi][1], af[mi][2], af[mi][3], b0, b1);
                    MMA16816(acc[mi][nj2 * 2 + 1], af[mi][0], af[mi][1], af[mi][2], af[mi][3], b2, b3);
                }
                addr = lT + (b_row + nj2 * 16) * (SROW * 2) + (b_kof + ks * 16) * 2;
                LDMX4(b0, b1, b2, b3, addr);
#pragma unroll
                for (int mi = 0; mi < 4; mi++) {
                    MMA16816(acc[mi][nj2 * 2],     af[mi][0], af[mi][1], af[mi][2], af[mi][3], b0, b1);
                    MMA16816(acc[mi][nj2 * 2 + 1], af[mi][0], af[mi][1], af[mi][2], af[mi][3], b2, b3);
                }
            }
        }
    }

    // epilogue: direct float2 stores to g_J
    const int mrow0 = bm * BM + wm * 64 + (lid >> 2);
    const int ncol0 = bn * BN + wn * 32 + (lid & 3) * 2;
#pragma unroll
    for (int mi = 0; mi < 4; mi++) {
#pragma unroll
        for (int nj = 0; nj < 4; nj++) {
            float* p0 = g_J + (size_t)(mrow0 + mi * 16) * N_DIM + ncol0 + nj * 8;
            float* p1 = g_J + (size_t)(mrow0 + mi * 16 + 8) * N_DIM + ncol0 + nj * 8;
            *reinterpret_cast<float2*>(p0) = make_float2(acc[mi][nj][0], acc[mi][nj][1]);
            *reinterpret_cast<float2*>(p1) = make_float2(acc[mi][nj][2], acc[mi][nj][3]);
        }
    }
}

// ---------------- LIF scan ----------------
__global__ __launch_bounds__(256) void lif_scan_kernel(float* __restrict__ out) {
    const int idx = blockIdx.x * blockDim.x + threadIdx.x;
    const size_t stride = (size_t)BATCH * DIM;
    float V = 0.0f, I = 0.0f;
#pragma unroll
    for (int t = 0; t < STEPS; t++) {
        float Vn = 0.95f * V + 0.05f * I;
        float s = (Vn >= 1.0f) ? 1.0f : 0.0f;
        V = Vn * (1.0f - s);
        I = 0.8f * I + g_J[(size_t)t * stride + idx];
        out[(size_t)t * stride + idx] = s;
    }
}

// ---------------- launch ----------------
extern "C" void kernel_launch(void* const* d_in, const int* in_sizes, int n_in,
                              void* d_out, int out_size) {
    const float* x = (const float*)d_in[0];   // [20, 512, 2048]
    const float* W = (const float*)d_in[1];   // [2048, 2048]
    float* out = (float*)d_out;

    conv_x_kernel<<<(M_TOT * K_DIM) / (256 * 4), 256>>>(x);
    conv_w_kernel<<<(N_DIM * K_DIM) / (256 * 4), 256>>>(W);

    cudaFuncSetAttribute(gemm_hmma_kernel,
                         cudaFuncAttributeMaxDynamicSharedMemorySize, SMEM_TOTAL);
    gemm_hmma_kernel<<<dim3(N_DIM / BN, M_TOT / BM), 256, SMEM_TOTAL>>>();

    lif_scan_kernel<<<(BATCH * DIM) / 256, 256>>>(out);
}

// round 4
// speedup vs baseline: 4.1857x; 1.0945x over previous
#include <cuda_runtime.h>
#include <cuda_bf16.h>
#include <cstdint>

#define STEPS 20
#define BATCH 512
#define DIM   2048
#define M_TOT (STEPS * BATCH)   // 10240
#define K_DIM DIM               // 2048
#define N_DIM DIM               // 2048

#define BM 128
#define BN 128
#define BK 64
#define NKITER (K_DIM / BK)      // 32
#define SROW 72                                  // padded smem row stride (elements), 144B
#define TILE_B (128 * SROW * 2)                  // 18432 B per 128x64 bf16 tile
#define STAGE_B (3 * TILE_B)                     // A + Bh + Bl = 55296 B
#define NSTAGE 2
#define SMEM_TOTAL (NSTAGE * STAGE_B)            // 110592 B

// ---------------- device globals (no allocs allowed) ----------------
__device__ __align__(256) __nv_bfloat16 g_Xb[(size_t)M_TOT * K_DIM];  // 42 MB
__device__ __align__(256) __nv_bfloat16 g_Wh[(size_t)N_DIM * K_DIM];  // 8 MB
__device__ __align__(256) __nv_bfloat16 g_Wl[(size_t)N_DIM * K_DIM];  // 8 MB
__device__ __align__(256) float         g_J [(size_t)M_TOT * N_DIM];  // 84 MB

// ---------------- PTX helpers ----------------
__device__ __forceinline__ uint32_t smem_u32(const void* p) {
    uint32_t a;
    asm("{ .reg .u64 t; cvta.to.shared.u64 t, %1; cvt.u32.u64 %0, t; }" : "=r"(a) : "l"(p));
    return a;
}
__device__ __forceinline__ void cp16(uint32_t s, const void* g) {
    asm volatile("cp.async.cg.shared.global [%0], [%1], 16;" :: "r"(s), "l"(g));
}
#define CP_COMMIT() asm volatile("cp.async.commit_group;" ::: "memory")

#define LDMX4(r0, r1, r2, r3, a) \
    asm volatile("ldmatrix.sync.aligned.m8n8.x4.shared.b16 {%0,%1,%2,%3}, [%4];" \
                 : "=r"(r0), "=r"(r1), "=r"(r2), "=r"(r3) : "r"(a))

#define MMA16816(c, a0, a1, a2, a3, b0, b1) \
    asm volatile("mma.sync.aligned.m16n8k16.row.col.f32.bf16.bf16.f32 " \
                 "{%0,%1,%2,%3}, {%4,%5,%6,%7}, {%8,%9}, {%0,%1,%2,%3};" \
                 : "+f"((c)[0]), "+f"((c)[1]), "+f"((c)[2]), "+f"((c)[3]) \
                 : "r"(a0), "r"(a1), "r"(a2), "r"(a3), "r"(b0), "r"(b1))

// ---------------- conversion kernels ----------------
__global__ __launch_bounds__(256) void conv_x_kernel(const float* __restrict__ x) {
    size_t i = ((size_t)blockIdx.x * 256 + threadIdx.x) * 4;
    float4 v = *reinterpret_cast<const float4*>(x + i);
    *reinterpret_cast<__nv_bfloat162*>(g_Xb + i)     = __floats2bfloat162_rn(v.x, v.y);
    *reinterpret_cast<__nv_bfloat162*>(g_Xb + i + 2) = __floats2bfloat162_rn(v.z, v.w);
}

__global__ __launch_bounds__(256) void conv_w_kernel(const float* __restrict__ w) {
    size_t i = ((size_t)blockIdx.x * 256 + threadIdx.x) * 4;
    float4 v = *reinterpret_cast<const float4*>(w + i);
    __nv_bfloat16 h0 = __float2bfloat16(v.x), h1 = __float2bfloat16(v.y);
    __nv_bfloat16 h2 = __float2bfloat16(v.z), h3 = __float2bfloat16(v.w);
    __nv_bfloat162 hi01; hi01.x = h0; hi01.y = h1;
    __nv_bfloat162 hi23; hi23.x = h2; hi23.y = h3;
    *reinterpret_cast<__nv_bfloat162*>(g_Wh + i)     = hi01;
    *reinterpret_cast<__nv_bfloat162*>(g_Wh + i + 2) = hi23;
    *reinterpret_cast<__nv_bfloat162*>(g_Wl + i) =
        __floats2bfloat162_rn(v.x - __bfloat162float(h0), v.y - __bfloat162float(h1));
    *reinterpret_cast<__nv_bfloat162*>(g_Wl + i + 2) =
        __floats2bfloat162_rn(v.z - __bfloat162float(h2), v.w - __bfloat162float(h3));
}

// ---------------- HMMA GEMM: J = Xb @ (Wh + Wl)^T ----------------
// Block 128x128x64, 8 warps (2m x 4n), warp tile 64x32, frags m16n8k16.
// 2-stage cp.async double buffer, prefetch distance 1.
__global__ __launch_bounds__(256, 2) void gemm_hmma_kernel() {
    extern __shared__ char smem[];
    const uint32_t sbase = smem_u32(smem);

    const int tid = threadIdx.x;
    const int wid = tid >> 5;
    const int lid = tid & 31;
    const int wm = wid & 1;          // 0..1  (m slices of 64)
    const int wn = wid >> 1;         // 0..3  (n slices of 32)
    const int bn = blockIdx.x;       // 0..15
    const int bm = blockIdx.y;       // 0..79

    const __nv_bfloat16* Ag = g_Xb + (size_t)(bm * BM) * K_DIM;
    const __nv_bfloat16* Hg = g_Wh + (size_t)(bn * BN) * K_DIM;
    const __nv_bfloat16* Lg = g_Wl + (size_t)(bn * BN) * K_DIM;

    auto sA = [&](int s) { return sbase + s * STAGE_B; };
    auto sH = [&](int s) { return sbase + s * STAGE_B + TILE_B; };
    auto sL = [&](int s) { return sbase + s * STAGE_B + 2 * TILE_B; };

    // global->smem: tile = 128 rows x 8 chunks(16B); 1024 chunks / 256 thr = 4 each.
    // chunk c: row = c>>3, byte col = (c&7)*16
    auto load_stage = [&](int s, int kt) {
        const int kof = kt * BK;
        const uint32_t a = sA(s), h = sH(s), l = sL(s);
#pragma unroll
        for (int it = 0; it < 4; it++) {
            const int c = tid + it * 256;
            const int r = c >> 3;
            const int cb = (c & 7) * 16;              // byte offset in 128B row data
            const uint32_t so = r * (SROW * 2) + cb;
            const size_t  go = (size_t)r * K_DIM + kof + cb / 2;
            cp16(a + so, Ag + go);
            cp16(h + so, Hg + go);
            cp16(l + so, Lg + go);
        }
        CP_COMMIT();
    };

    float acc[4][4][4];
#pragma unroll
    for (int i = 0; i < 4; i++)
#pragma unroll
        for (int j = 0; j < 4; j++)
#pragma unroll
            for (int r = 0; r < 4; r++) acc[i][j][r] = 0.0f;

    // ldmatrix per-thread components
    const int a_row = wm * 64 + (lid & 15);                      // + mi*16
    const int a_ke  = (lid >> 4) * 8;                            // + ks*16 (elements)
    const int b_row = wn * 32 + (lid & 7) + ((lid >> 4) << 3);   // + nj2*16
    const int b_ke  = ((lid >> 3) & 1) * 8;                      // + ks*16 (elements)

    load_stage(0, 0);

    for (int kt = 0; kt < NKITER; kt++) {
        if (kt + 1 < NKITER) load_stage((kt + 1) & 1, kt + 1);
        if (kt + 1 < NKITER) asm volatile("cp.async.wait_group 1;" ::: "memory");
        else                 asm volatile("cp.async.wait_group 0;" ::: "memory");
        __syncthreads();

        const int s = kt & 1;
        const uint32_t aT = sA(s), hT = sH(s), lT = sL(s);

#pragma unroll
        for (int ks = 0; ks < 4; ks++) {
            uint32_t af[4][4];
#pragma unroll
            for (int mi = 0; mi < 4; mi++) {
                uint32_t addr = aT + (a_row + mi * 16) * (SROW * 2) + (a_ke + ks * 16) * 2;
                LDMX4(af[mi][0], af[mi][1], af[mi][2], af[mi][3], addr);
            }
#pragma unroll
            for (int nj2 = 0; nj2 < 2; nj2++) {
                uint32_t b0, b1, b2, b3;
                uint32_t addr = hT + (b_row + nj2 * 16) * (SROW * 2) + (b_ke + ks * 16) * 2;
                LDMX4(b0, b1, b2, b3, addr);
#pragma unroll
                for (int mi = 0; mi < 4; mi++) {
                    MMA16816(acc[mi][nj2 * 2],     af[mi][0], af[mi][1], af[mi][2], af[mi][3], b0, b1);
                    MMA16816(acc[mi][nj2 * 2 + 1], af[mi][0], af[mi][1], af[mi][2], af[mi][3], b2, b3);
                }
                addr = lT + (b_row + nj2 * 16) * (SROW * 2) + (b_ke + ks * 16) * 2;
                LDMX4(b0, b1, b2, b3, addr);
#pragma unroll
                for (int mi = 0; mi < 4; mi++) {
                    MMA16816(acc[mi][nj2 * 2],     af[mi][0], af[mi][1], af[mi][2], af[mi][3], b0, b1);
                    MMA16816(acc[mi][nj2 * 2 + 1], af[mi][0], af[mi][1], af[mi][2], af[mi][3], b2, b3);
                }
            }
        }
        __syncthreads();   // protect stage s before kt+2's prefetch overwrites it
    }

    // epilogue
    const int mrow0 = bm * BM + wm * 64 + (lid >> 2);
    const int ncol0 = bn * BN + wn * 32 + (lid & 3) * 2;
#pragma unroll
    for (int mi = 0; mi < 4; mi++) {
#pragma unroll
        for (int nj = 0; nj < 4; nj++) {
            float* p0 = g_J + (size_t)(mrow0 + mi * 16) * N_DIM + ncol0 + nj * 8;
            float* p1 = g_J + (size_t)(mrow0 + mi * 16 + 8) * N_DIM + ncol0 + nj * 8;
            *reinterpret_cast<float2*>(p0) = make_float2(acc[mi][nj][0], acc[mi][nj][1]);
            *reinterpret_cast<float2*>(p1) = make_float2(acc[mi][nj][2], acc[mi][nj][3]);
        }
    }
}

// ---------------- LIF scan ----------------
__global__ __launch_bounds__(256) void lif_scan_kernel(float* __restrict__ out) {
    const int idx = blockIdx.x * blockDim.x + threadIdx.x;
    const size_t stride = (size_t)BATCH * DIM;
    float V = 0.0f, I = 0.0f;
#pragma unroll
    for (int t = 0; t < STEPS; t++) {
        float Vn = 0.95f * V + 0.05f * I;
        float s = (Vn >= 1.0f) ? 1.0f : 0.0f;
        V = Vn * (1.0f - s);
        I = 0.8f * I + g_J[(size_t)t * stride + idx];
        out[(size_t)t * stride + idx] = s;
    }
}

// ---------------- launch ----------------
extern "C" void kernel_launch(void* const* d_in, const int* in_sizes, int n_in,
                              void* d_out, int out_size) {
    const float* x = (const float*)d_in[0];   // [20, 512, 2048]
    const float* W = (const float*)d_in[1];   // [2048, 2048]
    float* out = (float*)d_out;

    conv_x_kernel<<<(M_TOT * K_DIM) / (256 * 4), 256>>>(x);
    conv_w_kernel<<<(N_DIM * K_DIM) / (256 * 4), 256>>>(W);

    cudaFuncSetAttribute(gemm_hmma_kernel,
                         cudaFuncAttributeMaxDynamicSharedMemorySize, SMEM_TOTAL);
    gemm_hmma_kernel<<<dim3(N_DIM / BN, M_TOT / BM), 256, SMEM_TOTAL>>>();

    lif_scan_kernel<<<(BATCH * DIM) / 256, 256>>>(out);
}